// round 1
// baseline (speedup 1.0000x reference)
#include <cuda_runtime.h>

#define NM 64
#define MAXN 262144

// ---------------- scratch (device globals; no runtime allocation) ----------
__device__ int g_counts[NM];
__device__ int g_offsets[NM];
__device__ int g_cursor[NM];
__device__ int g_perm[MAXN];

// ---------------- prep kernels --------------------------------------------
__global__ void zero_kernel() {
    if (threadIdx.x < NM) g_counts[threadIdx.x] = 0;
}

__global__ void hist_kernel(const int* __restrict__ idx, int N) {
    __shared__ int lc[NM];
    if (threadIdx.x < NM) lc[threadIdx.x] = 0;
    __syncthreads();
    for (int i = blockIdx.x * blockDim.x + threadIdx.x; i < N; i += gridDim.x * blockDim.x)
        atomicAdd(&lc[idx[i]], 1);
    __syncthreads();
    if (threadIdx.x < NM) atomicAdd(&g_counts[threadIdx.x], lc[threadIdx.x]);
}

__global__ void scan_kernel() {
    __shared__ int s[NM];
    int t = threadIdx.x;
    s[t] = g_counts[t];
    __syncthreads();
    if (t == 0) {
        int acc = 0;
        for (int i = 0; i < NM; i++) { int c = s[i]; s[i] = acc; acc += c; }
    }
    __syncthreads();
    g_offsets[t] = s[t];
    g_cursor[t]  = s[t];
}

// Privatized scatter: each block handles a contiguous slice, reserves ranges
// per model with one global atomic per (block, model).
__global__ void scatter_kernel(const int* __restrict__ idx, int N) {
    __shared__ int lc[NM];
    __shared__ int lbase[NM];
    int t = threadIdx.x;
    int per = (N + gridDim.x - 1) / gridDim.x;
    int lo = blockIdx.x * per;
    int hi = min(lo + per, N);
    if (t < NM) lc[t] = 0;
    __syncthreads();
    for (int i = lo + t; i < hi; i += blockDim.x)
        atomicAdd(&lc[idx[i]], 1);
    __syncthreads();
    if (t < NM) { lbase[t] = atomicAdd(&g_cursor[t], lc[t]); lc[t] = 0; }
    __syncthreads();
    for (int i = lo + t; i < hi; i += blockDim.x) {
        int m = idx[i];
        int r = atomicAdd(&lc[m], 1);
        g_perm[lbase[m] + r] = i;
    }
}

// ---------------- main compute kernel -------------------------------------
// SMEM layout (floats):
//   [0, 12288)      W1, W2, W3 (3 x 64x64)
//   [12288, 12672)  W0 (64x6)
//   [12672, 12864)  W4 (3x64)
//   [12864, 13056)  B0|G0|H0 (64 each)
//   [13056, 13632)  layers 1..3: B|G|H (192 floats each layer)
//   [13632, 13636)  B4 (3 + pad)
#define SMEM_FLOATS 13636

__device__ __forceinline__ void ln_relu(float* __restrict__ dst, const float* __restrict__ src,
                                        const float* __restrict__ G, const float* __restrict__ Hb) {
    float s0 = 0.f, s1 = 0.f, s2 = 0.f, s3 = 0.f;
#pragma unroll
    for (int i = 0; i < 64; i += 4) { s0 += src[i]; s1 += src[i+1]; s2 += src[i+2]; s3 += src[i+3]; }
    float mu = ((s0 + s1) + (s2 + s3)) * 0.015625f;
    float v0 = 0.f, v1 = 0.f, v2 = 0.f, v3 = 0.f;
#pragma unroll
    for (int i = 0; i < 64; i += 4) {
        float d0 = src[i]   - mu, d1 = src[i+1] - mu;
        float d2 = src[i+2] - mu, d3 = src[i+3] - mu;
        v0 = fmaf(d0, d0, v0); v1 = fmaf(d1, d1, v1);
        v2 = fmaf(d2, d2, v2); v3 = fmaf(d3, d3, v3);
    }
    float var = ((v0 + v1) + (v2 + v3)) * 0.015625f;
    float rs = rsqrtf(var + 1e-5f);
#pragma unroll
    for (int i = 0; i < 64; i++)
        dst[i] = fmaxf(fmaf((src[i] - mu) * rs, G[i], Hb[i]), 0.0f);
}

__global__ void __launch_bounds__(256, 1) mlp_kernel(
    const float* __restrict__ x,
    const float* __restrict__ W0, const float* __restrict__ B0,
    const float* __restrict__ G0, const float* __restrict__ H0,
    const float* __restrict__ W1, const float* __restrict__ B1,
    const float* __restrict__ G1, const float* __restrict__ H1,
    const float* __restrict__ W2, const float* __restrict__ B2,
    const float* __restrict__ G2, const float* __restrict__ H2,
    const float* __restrict__ W3, const float* __restrict__ B3,
    const float* __restrict__ G3, const float* __restrict__ H3,
    const float* __restrict__ W4, const float* __restrict__ B4,
    float* __restrict__ out)
{
    extern __shared__ float sm[];
    const int tid = threadIdx.x;
    const int m = blockIdx.y;
    const int cnt = g_counts[m];
    if ((int)blockIdx.x * 256 >= cnt) return;
    const int base = g_offsets[m];

    float* sW    = sm;
    float* sW0   = sm + 12288;
    float* sW4   = sm + 12672;
    float* sBGH0 = sm + 12864;
    float* sBGH  = sm + 13056;
    float* sB4   = sm + 13632;

    // cooperative weight load (float4)
    {
        float4* d = (float4*)sW;
        const float4* s1 = (const float4*)(W1 + m * 4096);
        const float4* s2 = (const float4*)(W2 + m * 4096);
        const float4* s3 = (const float4*)(W3 + m * 4096);
        for (int i = tid; i < 1024; i += 256) { d[i] = s1[i]; d[1024 + i] = s2[i]; d[2048 + i] = s3[i]; }
        if (tid < 96) ((float4*)sW0)[tid] = ((const float4*)(W0 + m * 384))[tid];
        if (tid < 48) ((float4*)sW4)[tid] = ((const float4*)(W4 + m * 192))[tid];
        if (tid < 16) {
            ((float4*)(sBGH0      ))[tid] = ((const float4*)(B0 + m * 64))[tid];
            ((float4*)(sBGH0 +  64))[tid] = ((const float4*)(G0 + m * 64))[tid];
            ((float4*)(sBGH0 + 128))[tid] = ((const float4*)(H0 + m * 64))[tid];
            ((float4*)(sBGH       ))[tid] = ((const float4*)(B1 + m * 64))[tid];
            ((float4*)(sBGH  +  64))[tid] = ((const float4*)(G1 + m * 64))[tid];
            ((float4*)(sBGH  + 128))[tid] = ((const float4*)(H1 + m * 64))[tid];
            ((float4*)(sBGH  + 192))[tid] = ((const float4*)(B2 + m * 64))[tid];
            ((float4*)(sBGH  + 256))[tid] = ((const float4*)(G2 + m * 64))[tid];
            ((float4*)(sBGH  + 320))[tid] = ((const float4*)(H2 + m * 64))[tid];
            ((float4*)(sBGH  + 384))[tid] = ((const float4*)(B3 + m * 64))[tid];
            ((float4*)(sBGH  + 448))[tid] = ((const float4*)(G3 + m * 64))[tid];
            ((float4*)(sBGH  + 512))[tid] = ((const float4*)(H3 + m * 64))[tid];
        }
        if (tid < 3) sB4[tid] = B4[m * 3 + tid];
    }
    __syncthreads();

    for (int pos0 = blockIdx.x * 256; pos0 < cnt; pos0 += gridDim.x * 256) {
        const int pos = pos0 + tid;
        const bool active = pos < cnt;
        const int s = active ? g_perm[base + pos] : 0;

        float xin[6];
#pragma unroll
        for (int j = 0; j < 6; j++) xin[j] = active ? x[s * 6 + j] : 0.0f;

        float h[64], nh[64];

        // layer 0: 6 -> 64
#pragma unroll
        for (int o = 0; o < 64; o++) {
            float acc = sBGH0[o];
#pragma unroll
            for (int f = 0; f < 6; f++) acc = fmaf(sW0[o * 6 + f], xin[f], acc);
            nh[o] = acc;
        }
        ln_relu(h, nh, sBGH0 + 64, sBGH0 + 128);

        // layers 1..3: 64 -> 64 (shared code body; weights via pointer)
#pragma unroll 1
        for (int l = 0; l < 3; l++) {
            const float* Wl = sW + l * 4096;
            const float* Bl = sBGH + l * 192;
#pragma unroll
            for (int o = 0; o < 64; o++) {
                float acc = Bl[o];
#pragma unroll
                for (int f = 0; f < 64; f += 4) {
                    float4 w = *(const float4*)(Wl + o * 64 + f);
                    acc = fmaf(w.x, h[f],     acc);
                    acc = fmaf(w.y, h[f + 1], acc);
                    acc = fmaf(w.z, h[f + 2], acc);
                    acc = fmaf(w.w, h[f + 3], acc);
                }
                nh[o] = acc;
            }
            ln_relu(h, nh, Bl + 64, Bl + 128);
        }

        // final layer: 64 -> 3
        if (active) {
            float* op = out + s * 3;
#pragma unroll
            for (int o = 0; o < 3; o++) {
                float acc = sB4[o];
#pragma unroll
                for (int f = 0; f < 64; f += 4) {
                    float4 w = *(const float4*)(sW4 + o * 64 + f);
                    acc = fmaf(w.x, h[f],     acc);
                    acc = fmaf(w.y, h[f + 1], acc);
                    acc = fmaf(w.z, h[f + 2], acc);
                    acc = fmaf(w.w, h[f + 3], acc);
                }
                op[o] = acc;
            }
        }
    }
}

// ---------------- launch ---------------------------------------------------
extern "C" void kernel_launch(void* const* d_in, const int* in_sizes, int n_in,
                              void* d_out, int out_size) {
    const float* x  = (const float*)d_in[0];
    const int* idx  = (const int*)d_in[1];
    const float* W0 = (const float*)d_in[2];
    const float* B0 = (const float*)d_in[3];
    const float* G0 = (const float*)d_in[4];
    const float* H0 = (const float*)d_in[5];
    const float* W1 = (const float*)d_in[6];
    const float* B1 = (const float*)d_in[7];
    const float* G1 = (const float*)d_in[8];
    const float* H1 = (const float*)d_in[9];
    const float* W2 = (const float*)d_in[10];
    const float* B2 = (const float*)d_in[11];
    const float* G2 = (const float*)d_in[12];
    const float* H2 = (const float*)d_in[13];
    const float* W3 = (const float*)d_in[14];
    const float* B3 = (const float*)d_in[15];
    const float* G3 = (const float*)d_in[16];
    const float* H3 = (const float*)d_in[17];
    const float* W4 = (const float*)d_in[18];
    const float* B4 = (const float*)d_in[19];
    float* out = (float*)d_out;

    int N = in_sizes[1];  // element count of indices
    if (N > MAXN) N = MAXN;

    cudaFuncSetAttribute(mlp_kernel, cudaFuncAttributeMaxDynamicSharedMemorySize,
                         SMEM_FLOATS * (int)sizeof(float));

    zero_kernel<<<1, 64>>>();
    hist_kernel<<<256, 256>>>(idx, N);
    scan_kernel<<<1, 64>>>();
    scatter_kernel<<<64, 256>>>(idx, N);

    dim3 grid(17, 64);
    mlp_kernel<<<grid, 256, SMEM_FLOATS * (int)sizeof(float)>>>(
        x, W0, B0, G0, H0, W1, B1, G1, H1, W2, B2, G2, H2, W3, B3, G3, H3, W4, B4, out);
}